// round 5
// baseline (speedup 1.0000x reference)
#include <cuda_runtime.h>
#include <math.h>

#define BB 4
#define LL 2048
#define DD 1024
#define MM (BB*LL)          // 8192 rows
#define PI_F 3.14159265358979323846f

// ---------------- scratch (device globals: allocation-free) ----------------
__device__ float g_xn  [(size_t)MM * DD];        // rmsnorm(x)
__device__ float g_u   [(size_t)MM * 3 * DD];    // in_proj output, (b*L+l, 3D)
__device__ float g_vg  [(size_t)BB * DD * LL];   // v*x1 after short conv, (b,d,l)
__device__ float g_x0  [(size_t)BB * DD * LL];   // x0 after short conv, (b,d,l)
__device__ float g_h2arr[(size_t)LL * 64];       // implicit filter hidden
__device__ float g_k   [(size_t)DD * LL];        // filter k, (d,l)
__device__ float g_yg  [(size_t)MM * DD];        // (y*x0) transposed to (b*L+l, d)
__device__ float g_hres[(size_t)MM * DD];        // h = out_proj(..)+x
__device__ float g_on  [(size_t)MM * DD];        // rmsnorm(h)
__device__ float g_ffn [(size_t)MM * 2 * DD];    // gelu(ffn1)

// ---------------- helpers ----------------
__device__ __forceinline__ float gelu_tanh(float x) {
    float x3 = x * x * x;
    return 0.5f * x * (1.f + tanhf(0.7978845608028654f * (x + 0.044715f * x3)));
}

// ---------------- implicit filter: hidden layer h2 (L,64) ----------------
__global__ void k_h2(const float* __restrict__ w1, const float* __restrict__ b1,
                     const float* __restrict__ f1, const float* __restrict__ w2,
                     const float* __restrict__ b2, const float* __restrict__ f2) {
    const int l = blockIdx.x;
    const int j = threadIdx.x;          // 0..63
    __shared__ float sh1[64];
    const float t  = (float)l * (1.f / (float)(LL - 1));
    const float wv = 2.f * PI_F * (float)l * (1.f / (float)LL);
    const float ang = 1e-4f * wv;
    const float z1 = cosf(ang), z2 = -sinf(ang);
    float p = w1[j*3+0]*t + w1[j*3+1]*z1 + w1[j*3+2]*z2 + b1[j];
    sh1[j] = sinf(f1[j] * p);
    __syncthreads();
    float s = b2[j];
#pragma unroll
    for (int q = 0; q < 64; q++) s = fmaf(w2[j*64+q], sh1[q], s);
    g_h2arr[l*64 + j] = sinf(f2[j] * s);
}

// ---------------- implicit filter: k[d][l] = (h2 @ w3^T) * exp-mod ----------------
__global__ void __launch_bounds__(256) k_filterk(const float* __restrict__ w3) {
    const int l0 = blockIdx.x << 6;
    const int d0 = blockIdx.y << 6;
    __shared__ float h2s[64 * 65];
    __shared__ float w3s[64 * 64];
    for (int i = threadIdx.x; i < 4096; i += 256) {
        int r = i >> 6, c = i & 63;
        h2s[r*65 + c] = g_h2arr[(size_t)(l0 + r)*64 + c];
        w3s[i] = w3[((size_t)d0 << 6) + i];
    }
    __syncthreads();
    const int lt   = threadIdx.x & 63;
    const int dgrp = threadIdx.x >> 6;   // 0..3
    const int l = l0 + lt;
    const float t = (float)l * (1.f / (float)(LL - 1));
#pragma unroll 1
    for (int ii = 0; ii < 16; ii++) {
        const int dd = dgrp*16 + ii;
        float s = 0.f;
#pragma unroll
        for (int q = 0; q < 64; q++) s = fmaf(h2s[lt*65+q], w3s[dd*64+q], s);
        const int dglob = d0 + dd;
        // |delta_d| = -(min_decay + (max-min)*d/(D-1)),  min=ln(.01)/1.5 max=ln(.01)/0.3
        const float absd = 3.070113457325394f + 12.280453829301576f * ((float)dglob * (1.f/1023.f));
        g_k[(size_t)dglob * LL + l] = s * expf(-t * absd);
    }
}

// ---------------- rmsnorm (one block per row) ----------------
__global__ void k_rmsnorm(const float* __restrict__ x, const float* __restrict__ w,
                          float* __restrict__ out) {
    const int row = blockIdx.x;
    const float* xr = x + (size_t)row * DD;
    float* orow = out + (size_t)row * DD;
    float s = 0.f;
    for (int i = threadIdx.x; i < DD; i += 256) { float v = xr[i]; s = fmaf(v, v, s); }
#pragma unroll
    for (int o = 16; o; o >>= 1) s += __shfl_xor_sync(0xffffffffu, s, o);
    __shared__ float red[8];
    if ((threadIdx.x & 31) == 0) red[threadIdx.x >> 5] = s;
    __syncthreads();
    float tt = 0.f;
#pragma unroll
    for (int i = 0; i < 8; i++) tt += red[i];
    const float scale = rsqrtf(tt * (1.f / (float)DD) + 1e-8f);
    for (int i = threadIdx.x; i < DD; i += 256) orow[i] = xr[i] * scale * w[i];
}

// ---------------- SGEMM: C[M,N] = A[M,K] @ W[N,K]^T + bias (+epilogue) ----------------
// EPI: 0 = bias only, 1 = bias + res, 2 = gelu(bias)
template<int EPI>
__global__ void __launch_bounds__(256, 2) sgemm_k(
    const float* __restrict__ A, const float* __restrict__ W,
    const float* __restrict__ bias, const float* __restrict__ res,
    float* __restrict__ C, int Mn, int Nn, int Kn)
{
    __shared__ float As[16][128];
    __shared__ float Bs[16][128];
    const int tid = threadIdx.x;
    const int bm = blockIdx.y * 128;
    const int bn = blockIdx.x * 128;
    const int lr = tid >> 2;            // 0..63
    const int lc = (tid & 3) << 2;      // 0,4,8,12
    const int ty = tid >> 4;            // 0..15
    const int tx = tid & 15;            // 0..15
    const float* Ag = A + (size_t)(bm + lr) * Kn + lc;
    const float* Wg = W + (size_t)(bn + lr) * Kn + lc;
    float acc[8][8];
#pragma unroll
    for (int i = 0; i < 8; i++)
#pragma unroll
        for (int j = 0; j < 8; j++) acc[i][j] = 0.f;

    for (int k0 = 0; k0 < Kn; k0 += 16) {
        float4 a0 = *(const float4*)(Ag + k0);
        float4 a1 = *(const float4*)(Ag + (size_t)64 * Kn + k0);
        float4 w0 = *(const float4*)(Wg + k0);
        float4 w1 = *(const float4*)(Wg + (size_t)64 * Kn + k0);
        __syncthreads();
        As[lc+0][lr]    = a0.x; As[lc+1][lr]    = a0.y; As[lc+2][lr]    = a0.z; As[lc+3][lr]    = a0.w;
        As[lc+0][lr+64] = a1.x; As[lc+1][lr+64] = a1.y; As[lc+2][lr+64] = a1.z; As[lc+3][lr+64] = a1.w;
        Bs[lc+0][lr]    = w0.x; Bs[lc+1][lr]    = w0.y; Bs[lc+2][lr]    = w0.z; Bs[lc+3][lr]    = w0.w;
        Bs[lc+0][lr+64] = w1.x; Bs[lc+1][lr+64] = w1.y; Bs[lc+2][lr+64] = w1.z; Bs[lc+3][lr+64] = w1.w;
        __syncthreads();
#pragma unroll
        for (int kk = 0; kk < 16; kk++) {
            float4 av0 = *(const float4*)&As[kk][ty*8];
            float4 av1 = *(const float4*)&As[kk][ty*8 + 4];
            float4 bv0 = *(const float4*)&Bs[kk][tx*8];
            float4 bv1 = *(const float4*)&Bs[kk][tx*8 + 4];
            float a[8] = {av0.x,av0.y,av0.z,av0.w,av1.x,av1.y,av1.z,av1.w};
            float b[8] = {bv0.x,bv0.y,bv0.z,bv0.w,bv1.x,bv1.y,bv1.z,bv1.w};
#pragma unroll
            for (int i = 0; i < 8; i++)
#pragma unroll
                for (int j = 0; j < 8; j++) acc[i][j] = fmaf(a[i], b[j], acc[i][j]);
        }
    }
#pragma unroll
    for (int i = 0; i < 8; i++) {
        const int m = bm + ty*8 + i;
        const size_t ro = (size_t)m * Nn;
#pragma unroll
        for (int j = 0; j < 8; j++) {
            const int n = bn + tx*8 + j;
            float v = acc[i][j] + bias[n];
            if (EPI == 1) v += res[ro + n];
            if (EPI == 2) v = gelu_tanh(v);
            C[ro + n] = v;
        }
    }
}

// ---------------- depthwise causal conv k=3 + gating prep ----------------
// reads g_u (b,l,3D), writes g_x0 and g_vg=v*x1 in (b,d,l)
__global__ void k_shortconv(const float* __restrict__ sfw, const float* __restrict__ sfb) {
    const int b = blockIdx.z;
    const int d = (blockIdx.y << 5) + threadIdx.x;
    const int lbase = (blockIdx.x << 5) + threadIdx.y;
    const float* ub = g_u + (size_t)b * LL * (3*DD);
#pragma unroll
    for (int i = 0; i < 4; i++) {
        const int l = lbase + (i << 3);
        float r[3];
#pragma unroll
        for (int c = 0; c < 3; c++) {
            const int ch = c*DD + d;
            const float w0 = sfw[ch*3+0], w1 = sfw[ch*3+1], w2 = sfw[ch*3+2];
            const float um2 = (l >= 2) ? ub[(size_t)(l-2)*(3*DD) + ch] : 0.f;
            const float um1 = (l >= 1) ? ub[(size_t)(l-1)*(3*DD) + ch] : 0.f;
            const float u0  = ub[(size_t)l*(3*DD) + ch];
            r[c] = w0*um2 + w1*um1 + w2*u0 + sfb[ch];
        }
        const size_t o = ((size_t)b*DD + d)*LL + l;
        g_x0[o] = r[0];
        g_vg[o] = r[2] * r[1];
    }
}

// ---------------- long causal conv, one CTA per (b,d) ----------------
// y[l] = sum_{m<=l} vg[m]*k[l-m] + vg[l]*bias[d];  out = y * x0, written transposed (b,l,d)
__global__ void __launch_bounds__(128) k_longconv(const float* __restrict__ fbias) {
    const int bd = blockIdx.x;
    const int b = bd >> 10;
    const int d = bd & (DD - 1);
    __shared__ __align__(16) float sv[LL];
    __shared__ float skp[LL + 8 + ((LL + 8) >> 5) + 1];   // swizzled k, 8 zero guard in front
    const float* vp = g_vg + (size_t)bd * LL;
    const float* kp = g_k  + (size_t)d  * LL;
    const int tid = threadIdx.x;
    for (int i = tid; i < LL/4; i += 128)
        ((float4*)sv)[i] = ((const float4*)vp)[i];
    for (int idx = tid; idx < LL + 8; idx += 128) {
        float v = (idx < 8) ? 0.f : kp[idx - 8];
        skp[idx + (idx >> 5)] = v;        // bank swizzle: kills lane-stride-8 conflicts
    }
    __syncthreads();
    const float bia = fbias[d];
    const float* x0p = g_x0 + (size_t)bd * LL;
    float* outp = g_yg + ((size_t)b * LL) * DD + d;

#pragma unroll
    for (int g = 0; g < 2; g++) {
        // reflection pairing: group0 la=8t (0..1016), group1 la=2040-8t (1024..2040)
        const int la = (g == 0) ? (tid << 3) : (2040 - (tid << 3));
        float acc[8];
#pragma unroll
        for (int j = 0; j < 8; j++) acc[j] = 0.f;
        const int mend = la + 8;          // always a multiple of 8
        for (int M0 = 0; M0 < mend; M0 += 8) {
            const int base = 1 + la - M0; // skp index of kr[0]; >= 1 always
            float kr[15];
#pragma unroll
            for (int i = 0; i < 15; i++) {
                const int idx = base + i;
                kr[i] = skp[idx + (idx >> 5)];
            }
            float svr[8];
#pragma unroll
            for (int mm = 0; mm < 8; mm++) svr[mm] = sv[M0 + mm];
#pragma unroll
            for (int mm = 0; mm < 8; mm++)
#pragma unroll
                for (int j = 0; j < 8; j++)
                    acc[j] = fmaf(svr[mm], kr[7 - mm + j], acc[j]);
        }
#pragma unroll
        for (int j = 0; j < 8; j++) {
            const int l = la + j;
            const float y = fmaf(sv[l], bia, acc[j]);
            outp[(size_t)l * DD] = y * x0p[l];
        }
    }
}

// ---------------- launch ----------------
extern "C" void kernel_launch(void* const* d_in, const int* in_sizes, int n_in,
                              void* d_out, int out_size) {
    const float* x          = (const float*)d_in[0];
    const float* norm_in_w  = (const float*)d_in[1];
    const float* in_proj_w  = (const float*)d_in[2];
    const float* in_proj_b  = (const float*)d_in[3];
    const float* sfw        = (const float*)d_in[4];
    const float* sfb        = (const float*)d_in[5];
    const float* mlp_w1     = (const float*)d_in[6];
    const float* mlp_b1     = (const float*)d_in[7];
    const float* freq1      = (const float*)d_in[8];
    const float* mlp_w2     = (const float*)d_in[9];
    const float* mlp_b2     = (const float*)d_in[10];
    const float* freq2      = (const float*)d_in[11];
    const float* mlp_w3     = (const float*)d_in[12];
    const float* filter_bias= (const float*)d_in[13];
    const float* out_proj_w = (const float*)d_in[14];
    const float* out_proj_b = (const float*)d_in[15];
    const float* norm_w     = (const float*)d_in[16];
    const float* ffn_w1     = (const float*)d_in[17];
    const float* ffn_b1     = (const float*)d_in[18];
    const float* ffn_w2     = (const float*)d_in[19];
    const float* ffn_b2     = (const float*)d_in[20];
    float* out = (float*)d_out;

    float *p_xn, *p_u, *p_yg, *p_h, *p_o, *p_ffn;
    cudaGetSymbolAddress((void**)&p_xn,  g_xn);
    cudaGetSymbolAddress((void**)&p_u,   g_u);
    cudaGetSymbolAddress((void**)&p_yg,  g_yg);
    cudaGetSymbolAddress((void**)&p_h,   g_hres);
    cudaGetSymbolAddress((void**)&p_o,   g_on);
    cudaGetSymbolAddress((void**)&p_ffn, g_ffn);

    // implicit filter (independent of main path)
    k_h2<<<LL, 64>>>(mlp_w1, mlp_b1, freq1, mlp_w2, mlp_b2, freq2);
    k_filterk<<<dim3(LL/64, DD/64), 256>>>(mlp_w3);

    // main path
    k_rmsnorm<<<MM, 256>>>(x, norm_in_w, p_xn);
    sgemm_k<0><<<dim3(3*DD/128, MM/128), 256>>>(p_xn, in_proj_w, in_proj_b, nullptr,
                                                p_u, MM, 3*DD, DD);
    k_shortconv<<<dim3(LL/32, DD/32, BB), dim3(32, 8)>>>(sfw, sfb);
    k_longconv<<<BB*DD, 128>>>(filter_bias);
    sgemm_k<1><<<dim3(DD/128, MM/128), 256>>>(p_yg, out_proj_w, out_proj_b, x,
                                              p_h, MM, DD, DD);
    k_rmsnorm<<<MM, 256>>>(p_h, norm_w, p_o);
    sgemm_k<2><<<dim3(2*DD/128, MM/128), 256>>>(p_o, ffn_w1, ffn_b1, nullptr,
                                                p_ffn, MM, 2*DD, DD);
    sgemm_k<1><<<dim3(DD/128, MM/128), 256>>>(p_ffn, ffn_w2, ffn_b2, p_h,
                                              out, MM, DD, 2*DD);
}